// round 1
// baseline (speedup 1.0000x reference)
#include <cuda_runtime.h>
#include <math.h>

#define BATCH 8
#define CHAN 128
#define PLANE 65536          // D*H*W = 4*128*128
#define NBC (BATCH * CHAN)   // 1024

__device__ float g_max[NBC];
__device__ float g_gate[NBC];

// ---------------------------------------------------------------------------
// Kernel 1: per-(b,c) global max over the contiguous 65536-element plane.
// One 512-thread block per plane; float4 loads, warp+block max reduce.
// ---------------------------------------------------------------------------
__global__ __launch_bounds__(512) void reduce_max_kernel(const float* __restrict__ x) {
    const int bc = blockIdx.x;
    const float4* p = reinterpret_cast<const float4*>(x) + (size_t)bc * (PLANE / 4);
    const int tid = threadIdx.x;

    float m = -INFINITY;
    #pragma unroll 8
    for (int i = tid; i < PLANE / 4; i += 512) {
        float4 v = p[i];
        m = fmaxf(m, fmaxf(fmaxf(v.x, v.y), fmaxf(v.z, v.w)));
    }
    // warp reduce
    #pragma unroll
    for (int off = 16; off > 0; off >>= 1)
        m = fmaxf(m, __shfl_xor_sync(0xffffffffu, m, off));

    __shared__ float sm[16];
    if ((tid & 31) == 0) sm[tid >> 5] = m;
    __syncthreads();
    if (tid < 16) {
        m = sm[tid];
        #pragma unroll
        for (int off = 8; off > 0; off >>= 1)
            m = fmaxf(m, __shfl_xor_sync(0x0000ffffu, m, off));
        if (tid == 0) g_max[bc] = m;
    }
}

// ---------------------------------------------------------------------------
// Kernel 2: tiny MLP gate.  gp[8,128] -> relu(gp@w1^T+b1) -> sigmoid(.@w2^T+b2)
// One block, 128 threads; thread o = output channel. All 8 batches per thread.
// ---------------------------------------------------------------------------
__global__ __launch_bounds__(128) void mlp_kernel(const float* __restrict__ w1,
                                                  const float* __restrict__ b1,
                                                  const float* __restrict__ w2,
                                                  const float* __restrict__ b2) {
    __shared__ float gp[BATCH][CHAN];
    __shared__ float hs[BATCH][CHAN];
    const int o = threadIdx.x;

    for (int i = o; i < NBC; i += 128)
        gp[i / CHAN][i % CHAN] = g_max[i];
    __syncthreads();

    float acc[BATCH];
    {
        const float bb = b1[o];
        #pragma unroll
        for (int b = 0; b < BATCH; b++) acc[b] = bb;
        const float* wrow = w1 + (size_t)o * CHAN;
        for (int c = 0; c < CHAN; c++) {
            const float w = wrow[c];
            #pragma unroll
            for (int b = 0; b < BATCH; b++) acc[b] = fmaf(gp[b][c], w, acc[b]);
        }
        #pragma unroll
        for (int b = 0; b < BATCH; b++) hs[b][o] = fmaxf(acc[b], 0.0f);
    }
    __syncthreads();
    {
        const float bb = b2[o];
        #pragma unroll
        for (int b = 0; b < BATCH; b++) acc[b] = bb;
        const float* wrow = w2 + (size_t)o * CHAN;
        for (int c = 0; c < CHAN; c++) {
            const float w = wrow[c];
            #pragma unroll
            for (int b = 0; b < BATCH; b++) acc[b] = fmaf(hs[b][c], w, acc[b]);
        }
        #pragma unroll
        for (int b = 0; b < BATCH; b++)
            g_gate[b * CHAN + o] = 1.0f / (1.0f + expf(-acc[b]));
    }
}

// ---------------------------------------------------------------------------
// Kernel 3: out = x * gate[bc], one float4 per thread.
// 16384 consecutive float4 share a gate -> broadcast-friendly load.
// ---------------------------------------------------------------------------
__global__ __launch_bounds__(256) void scale_kernel(const float* __restrict__ x,
                                                    float* __restrict__ out) {
    const size_t i = (size_t)blockIdx.x * 256 + threadIdx.x;   // float4 index
    const float g = g_gate[i >> 14];                           // 16384 f4 / plane
    float4 v = reinterpret_cast<const float4*>(x)[i];
    v.x *= g; v.y *= g; v.z *= g; v.w *= g;
    reinterpret_cast<float4*>(out)[i] = v;
}

// ---------------------------------------------------------------------------
extern "C" void kernel_launch(void* const* d_in, const int* in_sizes, int n_in,
                              void* d_out, int out_size) {
    const float* x  = (const float*)d_in[0];
    const float* w1 = (const float*)d_in[1];
    const float* b1 = (const float*)d_in[2];
    const float* w2 = (const float*)d_in[3];
    const float* b2 = (const float*)d_in[4];
    float* out = (float*)d_out;

    reduce_max_kernel<<<NBC, 512>>>(x);
    mlp_kernel<<<1, 128>>>(w1, b1, w2, b2);
    // total float4 elements: 8*128*65536/4 = 16,777,216 -> 65536 blocks of 256
    scale_kernel<<<65536, 256>>>(x, out);
}

// round 2
// speedup vs baseline: 1.0232x; 1.0232x over previous
#include <cuda_runtime.h>
#include <math.h>

#define BATCH 8
#define CHAN 128
#define PLANE 65536          // D*H*W = 4*128*128
#define NBC (BATCH * CHAN)   // 1024

__device__ float g_max[NBC];
__device__ float g_gate[NBC];

// ---------------------------------------------------------------------------
// Kernel 1: per-(b,c) global max over the contiguous 65536-element plane.
// One 512-thread block per plane; streaming float4 loads, 2 independent
// accumulators, warp+block max reduce.
// ---------------------------------------------------------------------------
__global__ __launch_bounds__(512) void reduce_max_kernel(const float* __restrict__ x) {
    const int bc = blockIdx.x;
    const float4* p = reinterpret_cast<const float4*>(x) + (size_t)bc * (PLANE / 4);
    const int tid = threadIdx.x;

    float m0 = -INFINITY, m1 = -INFINITY;
    // 16384 float4 / 512 threads = 32 iters; process 2 per loop (16 loops).
    #pragma unroll 4
    for (int i = tid; i < PLANE / 4; i += 1024) {
        float4 a = __ldcs(p + i);
        float4 b = __ldcs(p + i + 512);
        m0 = fmaxf(m0, fmaxf(fmaxf(a.x, a.y), fmaxf(a.z, a.w)));
        m1 = fmaxf(m1, fmaxf(fmaxf(b.x, b.y), fmaxf(b.z, b.w)));
    }
    float m = fmaxf(m0, m1);

    #pragma unroll
    for (int off = 16; off > 0; off >>= 1)
        m = fmaxf(m, __shfl_xor_sync(0xffffffffu, m, off));

    __shared__ float sm[16];
    if ((tid & 31) == 0) sm[tid >> 5] = m;
    __syncthreads();
    if (tid < 16) {
        m = sm[tid];
        #pragma unroll
        for (int off = 8; off > 0; off >>= 1)
            m = fmaxf(m, __shfl_xor_sync(0x0000ffffu, m, off));
        if (tid == 0) g_max[bc] = m;
    }
}

// ---------------------------------------------------------------------------
// Kernel 2: tiny MLP gate.  gp[8,128] -> relu(gp@w1^T+b1) -> sigmoid(.@w2^T+b2)
// One block, 128 threads; thread o = output channel. All 8 batches per thread.
// ---------------------------------------------------------------------------
__global__ __launch_bounds__(128) void mlp_kernel(const float* __restrict__ w1,
                                                  const float* __restrict__ b1,
                                                  const float* __restrict__ w2,
                                                  const float* __restrict__ b2) {
    __shared__ float gp[BATCH][CHAN];
    __shared__ float hs[BATCH][CHAN];
    const int o = threadIdx.x;

    for (int i = o; i < NBC; i += 128)
        gp[i / CHAN][i % CHAN] = g_max[i];
    __syncthreads();

    float acc[BATCH];
    {
        const float bb = b1[o];
        #pragma unroll
        for (int b = 0; b < BATCH; b++) acc[b] = bb;
        const float* wrow = w1 + (size_t)o * CHAN;
        for (int c = 0; c < CHAN; c++) {
            const float w = wrow[c];
            #pragma unroll
            for (int b = 0; b < BATCH; b++) acc[b] = fmaf(gp[b][c], w, acc[b]);
        }
        #pragma unroll
        for (int b = 0; b < BATCH; b++) hs[b][o] = fmaxf(acc[b], 0.0f);
    }
    __syncthreads();
    {
        const float bb = b2[o];
        #pragma unroll
        for (int b = 0; b < BATCH; b++) acc[b] = bb;
        const float* wrow = w2 + (size_t)o * CHAN;
        for (int c = 0; c < CHAN; c++) {
            const float w = wrow[c];
            #pragma unroll
            for (int b = 0; b < BATCH; b++) acc[b] = fmaf(hs[b][c], w, acc[b]);
        }
        #pragma unroll
        for (int b = 0; b < BATCH; b++)
            g_gate[b * CHAN + o] = 1.0f / (1.0f + expf(-acc[b]));
    }
}

// ---------------------------------------------------------------------------
// Kernel 3: out = x * gate[bc].
// 256 threads x 4 float4 per thread = 1024 consecutive float4 per block.
// A plane is 16384 float4 -> each block lies entirely inside one plane, so
// the gate is uniform per block: one broadcast load, zero per-element loads.
// Streaming hints: no reuse, keep L2 clean.
// ---------------------------------------------------------------------------
__global__ __launch_bounds__(256) void scale_kernel(const float* __restrict__ x,
                                                    float* __restrict__ out) {
    const float g = g_gate[blockIdx.x >> 4];   // 16 blocks per (b,c) plane
    const size_t base = (size_t)blockIdx.x * 1024 + threadIdx.x;
    const float4* xp = reinterpret_cast<const float4*>(x);
    float4* op = reinterpret_cast<float4*>(out);

    float4 v0 = __ldcs(xp + base);
    float4 v1 = __ldcs(xp + base + 256);
    float4 v2 = __ldcs(xp + base + 512);
    float4 v3 = __ldcs(xp + base + 768);

    v0.x *= g; v0.y *= g; v0.z *= g; v0.w *= g;
    v1.x *= g; v1.y *= g; v1.z *= g; v1.w *= g;
    v2.x *= g; v2.y *= g; v2.z *= g; v2.w *= g;
    v3.x *= g; v3.y *= g; v3.z *= g; v3.w *= g;

    __stcs(op + base,       v0);
    __stcs(op + base + 256, v1);
    __stcs(op + base + 512, v2);
    __stcs(op + base + 768, v3);
}

// ---------------------------------------------------------------------------
extern "C" void kernel_launch(void* const* d_in, const int* in_sizes, int n_in,
                              void* d_out, int out_size) {
    const float* x  = (const float*)d_in[0];
    const float* w1 = (const float*)d_in[1];
    const float* b1 = (const float*)d_in[2];
    const float* w2 = (const float*)d_in[3];
    const float* b2 = (const float*)d_in[4];
    float* out = (float*)d_out;

    reduce_max_kernel<<<NBC, 512>>>(x);
    mlp_kernel<<<1, 128>>>(w1, b1, w2, b2);
    // total float4: 16,777,216 -> 16384 blocks x (256 threads x 4 f4)
    scale_kernel<<<16384, 256>>>(x, out);
}